// round 5
// baseline (speedup 1.0000x reference)
#include <cuda_runtime.h>
#include <cuda_fp16.h>
#include <math.h>
#include <stdint.h>

#define C_IN   64
#define C_OUT  64
#define NBASIS 9
#define TILE_M 128
#define MAX_T  1600000
#define MAX_F  400000
#define BN_EPS 1e-3f

// ---- scratch (device globals; no allocation allowed) ----
__device__ __half g_contrib[(size_t)MAX_T * C_OUT];  // 204.8 MB (fp16)
__device__ float  g_prebn[(size_t)MAX_F * C_OUT];    // 102.4 MB
__device__ int    g_offs[MAX_F];
__device__ int    g_blk[1024];
__device__ float  g_stats[2 * C_OUT];

// ================= exclusive-scan of num_texture =================
__global__ void scan1_kernel(const int* __restrict__ cnt, int F) {
    __shared__ int s[1024];
    int tid = threadIdx.x;
    int f = blockIdx.x * 1024 + tid;
    int c = (f < F) ? cnt[f] : 0;
    s[tid] = c;
    __syncthreads();
    for (int off = 1; off < 1024; off <<= 1) {
        int v = (tid >= off) ? s[tid - off] : 0;
        __syncthreads();
        s[tid] += v;
        __syncthreads();
    }
    if (f < F) g_offs[f] = s[tid] - c;
    if (tid == 1023) g_blk[blockIdx.x] = s[1023];
}
__global__ void scan2_kernel(int nb) {
    __shared__ int s[1024];
    int tid = threadIdx.x;
    int c = (tid < nb) ? g_blk[tid] : 0;
    s[tid] = c;
    __syncthreads();
    for (int off = 1; off < 1024; off <<= 1) {
        int v = (tid >= off) ? s[tid - off] : 0;
        __syncthreads();
        s[tid] += v;
        __syncthreads();
    }
    if (tid < nb) g_blk[tid] = s[tid] - c;
}
__global__ void scan3_kernel(int F) {
    int f = blockIdx.x * 1024 + threadIdx.x;
    if (f < F) g_offs[f] += g_blk[blockIdx.x];
}

// ================= mma.sync GEMM, pipelined, bary folded in fp16 ==========
// contrib[t,o] = sum_k ( (x[t,:]*bary[t,k]) fp16 ) @ W_k[o,:]^T
//
// SMEM per CTA (swizzled 128B rows, XOR bits[6:4] ^= bits[9:7]):
//   Wh  : [row = kb*64+o][i] fp16, 576 rows x 128B      = 73728 B
//   Ax  : 2 buffers of [t][i] fp16, 128 rows x 128B     = 32768 B
//   Bsh : 2 buffers of [kb][t] fp16, 9*128 halfs        =  4608 B
#define SM_AX     73728
#define SM_BSH    (SM_AX + 2 * 16384)            // 106496
#define SMEM_GEMM (SM_BSH + 2 * 2304)            // 111104

__device__ __forceinline__ uint32_t swz(uint32_t b) { return b ^ ((b >> 3) & 0x70); }

#define MMA16816(d, a0, a1, a2, a3, b0, b1)                                 \
    asm volatile(                                                           \
        "mma.sync.aligned.m16n8k16.row.col.f32.f16.f16.f32 "                \
        "{%0,%1,%2,%3},{%4,%5,%6,%7},{%8,%9},{%0,%1,%2,%3};"                \
        : "+f"((d)[0]), "+f"((d)[1]), "+f"((d)[2]), "+f"((d)[3])            \
        : "r"(a0), "r"(a1), "r"(a2), "r"(a3), "r"(b0), "r"(b1))

__device__ __forceinline__ uint32_t hmul2u(uint32_t a, uint32_t b) {
    __half2 r = __hmul2(*(__half2*)&a, *(__half2*)&b);
    return *(uint32_t*)&r;
}

__global__ void __launch_bounds__(256, 2) gemm_mma_kernel(
    const float* __restrict__ X,     // [T, 64]
    const float* __restrict__ BARY,  // [T, 9]
    const float* __restrict__ W,     // [64, 64, 9]  (o, i, k)
    int T, int numTiles)
{
    extern __shared__ char sm[];
    __half* Bsh = (__half*)(sm + SM_BSH);

    const int tid  = threadIdx.x;
    const int wid  = tid >> 5;
    const int lane = tid & 31;
    const int gid  = lane >> 2;
    const int tid4 = lane & 3;
    const int warp_m = wid >> 1;     // 0..3
    const int warp_n = wid & 1;      // 0..1
    const int rbase  = warp_m * 32;

    // ---- Wh fill: swizzled [kb*64+o][i] fp16 ----
    for (int idx = tid; idx < C_OUT * C_IN * NBASIS; idx += 256) {
        int o   = idx / (C_IN * NBASIS);
        int rem = idx - o * (C_IN * NBASIS);
        int i   = rem / NBASIS;
        int kb  = rem - i * NBASIS;
        uint32_t byte = (uint32_t)(kb * 64 + o) * 128 + i * 2;
        *(__half*)(sm + swz(byte)) = __float2half_rn(W[idx]);
    }
    __syncthreads();

    // ---- prefetch helpers ----
    const int prow = tid >> 1;       // 0..127 texture row in tile
    const int phf  = tid & 1;        // which 32-channel half
    const int kb0  = phf ? 5 : 0;    // bary split: even loads k 0..4, odd 5..8
    const int nby  = phf ? 4 : 5;

    uint32_t pk[16];
    float    by[5];

    int tile = blockIdx.x;
    // prologue prefetch (tile always < numTiles since grid << tiles)
    {
        int t = tile * TILE_M + prow;
        if (t < T) {
            const float4* xp = (const float4*)(X + (size_t)t * C_IN + phf * 32);
            #pragma unroll
            for (int j = 0; j < 8; j++) {
                float4 v = xp[j];
                __half2 h0 = __floats2half2_rn(v.x, v.y);
                __half2 h1 = __floats2half2_rn(v.z, v.w);
                pk[2 * j]     = *(uint32_t*)&h0;
                pk[2 * j + 1] = *(uint32_t*)&h1;
            }
            #pragma unroll
            for (int j = 0; j < 5; j++)
                if (j < nby) by[j] = BARY[(size_t)t * NBASIS + kb0 + j];
        } else {
            #pragma unroll
            for (int j = 0; j < 16; j++) pk[j] = 0u;
            #pragma unroll
            for (int j = 0; j < 5; j++) by[j] = 0.0f;
        }
    }

    int buf = 0;
    for (; tile < numTiles; tile += gridDim.x) {
        const int t0 = tile * TILE_M;

        // ---- store phase: regs -> SMEM buffers ----
        {
            char*   AxB  = sm + SM_AX + buf * 16384;
            __half* BshB = Bsh + buf * 1152;
            uint32_t base = (uint32_t)prow * 128 + phf * 64;
            #pragma unroll
            for (int c = 0; c < 4; c++)
                *(uint4*)(AxB + swz(base + c * 16)) =
                    make_uint4(pk[4 * c], pk[4 * c + 1], pk[4 * c + 2], pk[4 * c + 3]);
            #pragma unroll
            for (int j = 0; j < 5; j++)
                if (j < nby) BshB[(kb0 + j) * 128 + prow] = __float2half_rn(by[j]);
        }
        __syncthreads();

        // ---- prefetch next tile (overlapped with MMA below) ----
        {
            int ntile = tile + gridDim.x;
            if (ntile < numTiles) {
                int t = ntile * TILE_M + prow;
                if (t < T) {
                    const float4* xp = (const float4*)(X + (size_t)t * C_IN + phf * 32);
                    #pragma unroll
                    for (int j = 0; j < 8; j++) {
                        float4 v = xp[j];
                        __half2 h0 = __floats2half2_rn(v.x, v.y);
                        __half2 h1 = __floats2half2_rn(v.z, v.w);
                        pk[2 * j]     = *(uint32_t*)&h0;
                        pk[2 * j + 1] = *(uint32_t*)&h1;
                    }
                    #pragma unroll
                    for (int j = 0; j < 5; j++)
                        if (j < nby) by[j] = BARY[(size_t)t * NBASIS + kb0 + j];
                } else {
                    #pragma unroll
                    for (int j = 0; j < 16; j++) pk[j] = 0u;
                    #pragma unroll
                    for (int j = 0; j < 5; j++) by[j] = 0.0f;
                }
            }
        }

        // ---- A fragments (raw x, fp16) ----
        const char*   AxB  = sm + SM_AX + buf * 16384;
        const __half* BshB = Bsh + buf * 1152;

        uint32_t afr[2][4][4];
        #pragma unroll
        for (int mt = 0; mt < 2; mt++) {
            uint32_t r = rbase + mt * 16 + gid;
            #pragma unroll
            for (int ks = 0; ks < 4; ks++) {
                uint32_t col = ks * 32 + tid4 * 4;
                afr[mt][ks][0] = *(const uint32_t*)(AxB + swz(r * 128 + col));
                afr[mt][ks][1] = *(const uint32_t*)(AxB + swz((r + 8) * 128 + col));
                afr[mt][ks][2] = *(const uint32_t*)(AxB + swz(r * 128 + col + 16));
                afr[mt][ks][3] = *(const uint32_t*)(AxB + swz((r + 8) * 128 + col + 16));
            }
        }

        float acc[2][4][4];
        #pragma unroll
        for (int mt = 0; mt < 2; mt++)
            #pragma unroll
            for (int nt = 0; nt < 4; nt++)
                #pragma unroll
                for (int e = 0; e < 4; e++) acc[mt][nt][e] = 0.0f;

        #pragma unroll
        for (int kb = 0; kb < NBASIS; kb++) {
            // bary half2 broadcasts per mt / row half
            uint32_t bb0[2], bb1[2];
            #pragma unroll
            for (int mt = 0; mt < 2; mt++) {
                int r = rbase + mt * 16 + gid;
                __half2 h0 = __half2half2(BshB[kb * 128 + r]);
                __half2 h1 = __half2half2(BshB[kb * 128 + r + 8]);
                bb0[mt] = *(uint32_t*)&h0;
                bb1[mt] = *(uint32_t*)&h1;
            }

            #pragma unroll
            for (int ks = 0; ks < 4; ks++) {
                // scale A frags by bary (fp16)
                uint32_t sa[2][4];
                #pragma unroll
                for (int mt = 0; mt < 2; mt++) {
                    sa[mt][0] = hmul2u(afr[mt][ks][0], bb0[mt]);
                    sa[mt][1] = hmul2u(afr[mt][ks][1], bb1[mt]);
                    sa[mt][2] = hmul2u(afr[mt][ks][2], bb0[mt]);
                    sa[mt][3] = hmul2u(afr[mt][ks][3], bb1[mt]);
                }
                #pragma unroll
                for (int nt = 0; nt < 4; nt++) {
                    uint32_t rowb = (uint32_t)(kb * 64 + warp_n * 32 + nt * 8 + gid) * 128;
                    uint32_t col  = ks * 32 + tid4 * 4;
                    uint32_t b0 = *(const uint32_t*)(sm + swz(rowb + col));
                    uint32_t b1 = *(const uint32_t*)(sm + swz(rowb + col + 16));
                    MMA16816(acc[0][nt], sa[0][0], sa[0][1], sa[0][2], sa[0][3], b0, b1);
                    MMA16816(acc[1][nt], sa[1][0], sa[1][1], sa[1][2], sa[1][3], b0, b1);
                }
            }
        }

        // ---- store 32x32 warp tile as fp16 ----
        #pragma unroll
        for (int mt = 0; mt < 2; mt++) {
            int t = t0 + rbase + mt * 16 + gid;
            #pragma unroll
            for (int nt = 0; nt < 4; nt++) {
                int col = warp_n * 32 + nt * 8 + tid4 * 2;
                if (t < T) {
                    __half2 h = __floats2half2_rn(acc[mt][nt][0], acc[mt][nt][1]);
                    *(__half2*)&g_contrib[(size_t)t * C_OUT + col] = h;
                }
                if (t + 8 < T) {
                    __half2 h = __floats2half2_rn(acc[mt][nt][2], acc[mt][nt][3]);
                    *(__half2*)&g_contrib[(size_t)(t + 8) * C_OUT + col] = h;
                }
            }
        }
        buf ^= 1;
        // single barrier per tile: double buffering makes the second one redundant
    }
}

// ================= facet mean + bias + relu + fused BN stats =================
__global__ void facet_kernel(const int* __restrict__ cnt,
                             const float* __restrict__ bias, int F) {
    __shared__ float ssum[64], ssq[64];
    int tid = threadIdx.x;
    if (tid < 64) { ssum[tid] = 0.0f; ssq[tid] = 0.0f; }
    __syncthreads();

    int gw   = (blockIdx.x * blockDim.x + tid) >> 5;
    int lane = tid & 31;
    int nw   = (gridDim.x * blockDim.x) >> 5;
    float b0 = bias[2 * lane];
    float b1 = bias[2 * lane + 1];
    float a0 = 0.0f, a1 = 0.0f, q0 = 0.0f, q1 = 0.0f;

    for (int f = gw; f < F; f += nw) {
        int start = g_offs[f];
        int c = cnt[f];
        float s0 = 0.0f, s1 = 0.0f;
        for (int r = 0; r < c; r++) {
            const __half2* row = (const __half2*)(g_contrib + (size_t)(start + r) * C_OUT);
            float2 v = __half22float2(row[lane]);
            s0 += v.x;
            s1 += v.y;
        }
        float inv = (c > 0) ? (1.0f / (float)c) : 0.0f;
        float v0 = fmaxf(s0 * inv + b0, 0.0f);
        float v1 = fmaxf(s1 * inv + b1, 0.0f);
        *(float2*)&g_prebn[(size_t)f * C_OUT + 2 * lane] = make_float2(v0, v1);
        a0 += v0; q0 += v0 * v0;
        a1 += v1; q1 += v1 * v1;
    }
    atomicAdd(&ssum[2 * lane],     a0);
    atomicAdd(&ssq[2 * lane],      q0);
    atomicAdd(&ssum[2 * lane + 1], a1);
    atomicAdd(&ssq[2 * lane + 1],  q1);
    __syncthreads();
    if (tid < 64) {
        atomicAdd(&g_stats[tid],      ssum[tid]);
        atomicAdd(&g_stats[64 + tid], ssq[tid]);
    }
}

__global__ void zero_stats_kernel() {
    if (threadIdx.x < 2 * C_OUT) g_stats[threadIdx.x] = 0.0f;
}

// ================= batchnorm apply =================
__global__ void bn_kernel(const float* __restrict__ gamma,
                          const float* __restrict__ beta,
                          float* __restrict__ out, int F) {
    int idx = blockIdx.x * blockDim.x + threadIdx.x;
    int total = F * (C_OUT / 4);
    float invF = 1.0f / (float)F;
    for (; idx < total; idx += gridDim.x * blockDim.x) {
        int o = (idx & 15) * 4;
        float4 v = *(const float4*)&g_prebn[(size_t)idx * 4];
        float4 r;
        #pragma unroll
        for (int j = 0; j < 4; j++) {
            float mu  = g_stats[o + j] * invF;
            float var = g_stats[C_OUT + o + j] * invF - mu * mu;
            float sc  = rsqrtf(var + BN_EPS) * gamma[o + j];
            float bb  = beta[o + j];
            float x   = (&v.x)[j];
            (&r.x)[j] = (x - mu) * sc + bb;
        }
        *(float4*)&out[(size_t)idx * 4] = r;
    }
}

// ================= launch =================
extern "C" void kernel_launch(void* const* d_in, const int* in_sizes, int n_in,
                              void* d_out, int out_size) {
    const float* X     = (const float*)d_in[0];
    const float* BARY  = (const float*)d_in[1];
    const float* W     = (const float*)d_in[2];
    const float* bias  = (const float*)d_in[3];
    const float* gamma = (const float*)d_in[4];
    const float* beta  = (const float*)d_in[5];
    const int*   cnt   = (const int*)d_in[6];

    int T = in_sizes[0] / C_IN;
    int F = in_sizes[6];
    int numTiles = (T + TILE_M - 1) / TILE_M;

    int sms = 148;
    cudaDeviceGetAttribute(&sms, cudaDevAttrMultiProcessorCount, 0);
    cudaFuncSetAttribute(gemm_mma_kernel, cudaFuncAttributeMaxDynamicSharedMemorySize, SMEM_GEMM);

    int nb = (F + 1023) / 1024;
    scan1_kernel<<<nb, 1024>>>(cnt, F);
    scan2_kernel<<<1, 1024>>>(nb);
    scan3_kernel<<<nb, 1024>>>(F);

    gemm_mma_kernel<<<2 * sms, 256, SMEM_GEMM>>>(X, BARY, W, T, numTiles);

    zero_stats_kernel<<<1, 128>>>();
    facet_kernel<<<2048, 256>>>(cnt, bias, F);

    bn_kernel<<<2048, 256>>>(gamma, beta, (float*)d_out, F);
}

// round 6
// speedup vs baseline: 1.5059x; 1.5059x over previous
#include <cuda_runtime.h>
#include <cuda_fp16.h>
#include <math.h>
#include <stdint.h>

#define C_IN   64
#define C_OUT  64
#define NBASIS 9
#define TILE_M 128
#define MAX_T  1600000
#define MAX_F  400000
#define BN_EPS 1e-3f

// ---- scratch (device globals; no allocation allowed) ----
__device__ __half g_contrib[(size_t)MAX_T * C_OUT];  // 204.8 MB (fp16)
__device__ float  g_prebn[(size_t)MAX_F * C_OUT];    // 102.4 MB
__device__ int    g_offs[MAX_F];
__device__ int    g_blk[1024];
__device__ float  g_stats[2 * C_OUT];

// ================= exclusive-scan of num_texture =================
__global__ void scan1_kernel(const int* __restrict__ cnt, int F) {
    __shared__ int s[1024];
    int tid = threadIdx.x;
    int f = blockIdx.x * 1024 + tid;
    int c = (f < F) ? cnt[f] : 0;
    s[tid] = c;
    __syncthreads();
    for (int off = 1; off < 1024; off <<= 1) {
        int v = (tid >= off) ? s[tid - off] : 0;
        __syncthreads();
        s[tid] += v;
        __syncthreads();
    }
    if (f < F) g_offs[f] = s[tid] - c;
    if (tid == 1023) g_blk[blockIdx.x] = s[1023];
}
__global__ void scan2_kernel(int nb) {
    __shared__ int s[1024];
    int tid = threadIdx.x;
    int c = (tid < nb) ? g_blk[tid] : 0;
    s[tid] = c;
    __syncthreads();
    for (int off = 1; off < 1024; off <<= 1) {
        int v = (tid >= off) ? s[tid - off] : 0;
        __syncthreads();
        s[tid] += v;
        __syncthreads();
    }
    if (tid < nb) g_blk[tid] = s[tid] - c;
}
__global__ void scan3_kernel(int F) {
    int f = blockIdx.x * 1024 + threadIdx.x;
    if (f < F) g_offs[f] += g_blk[blockIdx.x];
}

// ================= mma.sync GEMM: R4 core + double-buffer pipeline ========
// contrib[t,o] = sum_k bary[t,k] * ( sum_i x[t,i] * W[o,i,k] )
//
// SMEM per CTA (pad-72 rows, conflict-free):
//   Wh : [(k*64 + o)*72 + i] fp16   9*64*72*2 = 82944 B
//   Ax : 2 x [t*72 + i]      fp16   128*72*2  = 18432 B each
//   Bs : 2 x [t*9 + k]       fp32   128*9*4   =  4608 B each
#define SM_WH   0
#define SM_AX   82944
#define AX_BUF  (TILE_M * 72 * 2)                       // 18432
#define SM_BS   (SM_AX + 2 * AX_BUF)                    // 119808
#define BS_BUF  (TILE_M * NBASIS)                       // floats
#define SMEM_GEMM (SM_BS + 2 * BS_BUF * 4)              // 129024

#define MMA16816(d, a0, a1, a2, a3, b0, b1)                                 \
    asm volatile(                                                           \
        "mma.sync.aligned.m16n8k16.row.col.f32.f16.f16.f32 "                \
        "{%0,%1,%2,%3},{%4,%5,%6,%7},{%8,%9},{%0,%1,%2,%3};"                \
        : "+f"((d)[0]), "+f"((d)[1]), "+f"((d)[2]), "+f"((d)[3])            \
        : "r"(a0), "r"(a1), "r"(a2), "r"(a3), "r"(b0), "r"(b1))

__global__ void __launch_bounds__(256, 2) gemm_mma_kernel(
    const float* __restrict__ X,     // [T, 64]
    const float* __restrict__ BARY,  // [T, 9]
    const float* __restrict__ W,     // [64, 64, 9]  (o, i, k)
    int T, int numTiles)
{
    extern __shared__ char sm[];
    __half* Wh = (__half*)(sm + SM_WH);
    float*  Bs = (float*)(sm + SM_BS);

    const int tid  = threadIdx.x;
    const int wid  = tid >> 5;
    const int lane = tid & 31;
    const int gid  = lane >> 2;
    const int tid4 = lane & 3;
    const int warp_m = wid >> 1;     // 0..3
    const int warp_n = wid & 1;      // 0..1
    const int rbase  = warp_m * 32;

    // ---- convert W once: Wh[k][o][i] fp16, pad-72 ----
    for (int idx = tid; idx < C_OUT * C_IN * NBASIS; idx += 256) {
        int o   = idx / (C_IN * NBASIS);
        int rem = idx - o * (C_IN * NBASIS);
        int i   = rem / NBASIS;
        int k   = rem - i * NBASIS;
        Wh[(k * 64 + o) * 72 + i] = __float2half_rn(W[idx]);
    }

    // ---- prefetch lane mapping ----
    const int prow = tid >> 1;       // 0..127
    const int phf  = tid & 1;        // channel half
    const int kb0  = phf ? 5 : 0;    // bary split across the 2 threads of a row
    const int nby  = phf ? 4 : 5;

    uint32_t pk[16];
    float    by[5];

    int tile = blockIdx.x;
    // prologue prefetch
    {
        int t = tile * TILE_M + prow;
        if (t < T) {
            const float4* xp = (const float4*)(X + (size_t)t * C_IN + phf * 32);
            #pragma unroll
            for (int j = 0; j < 8; j++) {
                float4 v = xp[j];
                __half2 h0 = __floats2half2_rn(v.x, v.y);
                __half2 h1 = __floats2half2_rn(v.z, v.w);
                pk[2 * j]     = *(uint32_t*)&h0;
                pk[2 * j + 1] = *(uint32_t*)&h1;
            }
            #pragma unroll
            for (int j = 0; j < 5; j++)
                if (j < nby) by[j] = BARY[(size_t)t * NBASIS + kb0 + j];
        } else {
            #pragma unroll
            for (int j = 0; j < 16; j++) pk[j] = 0u;
            #pragma unroll
            for (int j = 0; j < 5; j++) by[j] = 0.0f;
        }
    }

    int buf = 0;
    for (; tile < numTiles; tile += gridDim.x) {
        const int t0 = tile * TILE_M;

        // ---- store phase: regs -> SMEM buffer ----
        {
            __half* AxB = (__half*)(sm + SM_AX + buf * AX_BUF);
            float*  BsB = Bs + buf * BS_BUF;
            uint4* dst = (uint4*)(AxB + prow * 72 + phf * 32);
            #pragma unroll
            for (int c = 0; c < 4; c++)
                dst[c] = make_uint4(pk[4 * c], pk[4 * c + 1], pk[4 * c + 2], pk[4 * c + 3]);
            #pragma unroll
            for (int j = 0; j < 5; j++)
                if (j < nby) BsB[prow * NBASIS + kb0 + j] = by[j];
        }
        __syncthreads();

        // ---- prefetch next tile (overlaps with MMA work below) ----
        {
            int ntile = tile + gridDim.x;
            if (ntile < numTiles) {
                int t = ntile * TILE_M + prow;
                if (t < T) {
                    const float4* xp = (const float4*)(X + (size_t)t * C_IN + phf * 32);
                    #pragma unroll
                    for (int j = 0; j < 8; j++) {
                        float4 v = xp[j];
                        __half2 h0 = __floats2half2_rn(v.x, v.y);
                        __half2 h1 = __floats2half2_rn(v.z, v.w);
                        pk[2 * j]     = *(uint32_t*)&h0;
                        pk[2 * j + 1] = *(uint32_t*)&h1;
                    }
                    #pragma unroll
                    for (int j = 0; j < 5; j++)
                        if (j < nby) by[j] = BARY[(size_t)t * NBASIS + kb0 + j];
                } else {
                    #pragma unroll
                    for (int j = 0; j < 16; j++) pk[j] = 0u;
                    #pragma unroll
                    for (int j = 0; j < 5; j++) by[j] = 0.0f;
                }
            }
        }

        const __half* AxB = (const __half*)(sm + SM_AX + buf * AX_BUF);
        const float*  BsB = Bs + buf * BS_BUF;

        float acc[2][4][4];
        #pragma unroll
        for (int mt = 0; mt < 2; mt++)
            #pragma unroll
            for (int nt = 0; nt < 4; nt++)
                #pragma unroll
                for (int e = 0; e < 4; e++) acc[mt][nt][e] = 0.0f;

        #pragma unroll 1
        for (int kb = 0; kb < NBASIS; kb++) {
            float tac[2][4][4];
            #pragma unroll
            for (int mt = 0; mt < 2; mt++)
                #pragma unroll
                for (int nt = 0; nt < 4; nt++)
                    #pragma unroll
                    for (int e = 0; e < 4; e++) tac[mt][nt][e] = 0.0f;

            #pragma unroll
            for (int ks = 0; ks < 4; ks++) {
                // A fragments for this ks (per-ks load: keeps regs low for prefetch)
                uint32_t af[2][4];
                #pragma unroll
                for (int mt = 0; mt < 2; mt++) {
                    int r  = rbase + mt * 16 + gid;
                    int kk = ks * 16 + tid4 * 2;
                    af[mt][0] = *(const uint32_t*)(AxB + r * 72 + kk);
                    af[mt][1] = *(const uint32_t*)(AxB + (r + 8) * 72 + kk);
                    af[mt][2] = *(const uint32_t*)(AxB + r * 72 + kk + 8);
                    af[mt][3] = *(const uint32_t*)(AxB + (r + 8) * 72 + kk + 8);
                }
                #pragma unroll
                for (int nt = 0; nt < 4; nt++) {
                    int n = warp_n * 32 + nt * 8 + gid;
                    const __half* bp = Wh + (kb * 64 + n) * 72 + ks * 16 + tid4 * 2;
                    uint32_t b0 = *(const uint32_t*)bp;
                    uint32_t b1 = *(const uint32_t*)(bp + 8);
                    MMA16816(tac[0][nt], af[0][0], af[0][1], af[0][2], af[0][3], b0, b1);
                    MMA16816(tac[1][nt], af[1][0], af[1][1], af[1][2], af[1][3], b0, b1);
                }
            }

            // fold with fp32 bary (off the MMA critical path)
            #pragma unroll
            for (int mt = 0; mt < 2; mt++) {
                float blo = BsB[(rbase + mt * 16 + gid) * NBASIS + kb];
                float bhi = BsB[(rbase + mt * 16 + gid + 8) * NBASIS + kb];
                #pragma unroll
                for (int nt = 0; nt < 4; nt++) {
                    acc[mt][nt][0] += blo * tac[mt][nt][0];
                    acc[mt][nt][1] += blo * tac[mt][nt][1];
                    acc[mt][nt][2] += bhi * tac[mt][nt][2];
                    acc[mt][nt][3] += bhi * tac[mt][nt][3];
                }
            }
        }

        // ---- store 32x32 warp tile as fp16 ----
        #pragma unroll
        for (int mt = 0; mt < 2; mt++) {
            int t = t0 + rbase + mt * 16 + gid;
            #pragma unroll
            for (int nt = 0; nt < 4; nt++) {
                int col = warp_n * 32 + nt * 8 + tid4 * 2;
                if (t < T) {
                    __half2 h = __floats2half2_rn(acc[mt][nt][0], acc[mt][nt][1]);
                    *(__half2*)&g_contrib[(size_t)t * C_OUT + col] = h;
                }
                if (t + 8 < T) {
                    __half2 h = __floats2half2_rn(acc[mt][nt][2], acc[mt][nt][3]);
                    *(__half2*)&g_contrib[(size_t)(t + 8) * C_OUT + col] = h;
                }
            }
        }
        buf ^= 1;
        // single barrier per tile: double buffer + program order make the
        // second barrier redundant (compute_n precedes barrier_{n+1} in
        // every warp, so buf_n is never overwritten while readable).
    }
}

// ================= facet mean + bias + relu + fused BN stats =================
__global__ void facet_kernel(const int* __restrict__ cnt,
                             const float* __restrict__ bias, int F) {
    __shared__ float ssum[64], ssq[64];
    int tid = threadIdx.x;
    if (tid < 64) { ssum[tid] = 0.0f; ssq[tid] = 0.0f; }
    __syncthreads();

    int gw   = (blockIdx.x * blockDim.x + tid) >> 5;
    int lane = tid & 31;
    int nw   = (gridDim.x * blockDim.x) >> 5;
    float b0 = bias[2 * lane];
    float b1 = bias[2 * lane + 1];
    float a0 = 0.0f, a1 = 0.0f, q0 = 0.0f, q1 = 0.0f;

    for (int f = gw; f < F; f += nw) {
        int start = g_offs[f];
        int c = cnt[f];
        float s0 = 0.0f, s1 = 0.0f;
        for (int r = 0; r < c; r++) {
            const __half2* row = (const __half2*)(g_contrib + (size_t)(start + r) * C_OUT);
            float2 v = __half22float2(row[lane]);
            s0 += v.x;
            s1 += v.y;
        }
        float inv = (c > 0) ? (1.0f / (float)c) : 0.0f;
        float v0 = fmaxf(s0 * inv + b0, 0.0f);
        float v1 = fmaxf(s1 * inv + b1, 0.0f);
        *(float2*)&g_prebn[(size_t)f * C_OUT + 2 * lane] = make_float2(v0, v1);
        a0 += v0; q0 += v0 * v0;
        a1 += v1; q1 += v1 * v1;
    }
    atomicAdd(&ssum[2 * lane],     a0);
    atomicAdd(&ssq[2 * lane],      q0);
    atomicAdd(&ssum[2 * lane + 1], a1);
    atomicAdd(&ssq[2 * lane + 1],  q1);
    __syncthreads();
    if (tid < 64) {
        atomicAdd(&g_stats[tid],      ssum[tid]);
        atomicAdd(&g_stats[64 + tid], ssq[tid]);
    }
}

__global__ void zero_stats_kernel() {
    if (threadIdx.x < 2 * C_OUT) g_stats[threadIdx.x] = 0.0f;
}

// ================= batchnorm apply =================
__global__ void bn_kernel(const float* __restrict__ gamma,
                          const float* __restrict__ beta,
                          float* __restrict__ out, int F) {
    int idx = blockIdx.x * blockDim.x + threadIdx.x;
    int total = F * (C_OUT / 4);
    float invF = 1.0f / (float)F;
    for (; idx < total; idx += gridDim.x * blockDim.x) {
        int o = (idx & 15) * 4;
        float4 v = *(const float4*)&g_prebn[(size_t)idx * 4];
        float4 r;
        #pragma unroll
        for (int j = 0; j < 4; j++) {
            float mu  = g_stats[o + j] * invF;
            float var = g_stats[C_OUT + o + j] * invF - mu * mu;
            float sc  = rsqrtf(var + BN_EPS) * gamma[o + j];
            float bb  = beta[o + j];
            float x   = (&v.x)[j];
            (&r.x)[j] = (x - mu) * sc + bb;
        }
        *(float4*)&out[(size_t)idx * 4] = r;
    }
}

// ================= launch =================
extern "C" void kernel_launch(void* const* d_in, const int* in_sizes, int n_in,
                              void* d_out, int out_size) {
    const float* X     = (const float*)d_in[0];
    const float* BARY  = (const float*)d_in[1];
    const float* W     = (const float*)d_in[2];
    const float* bias  = (const float*)d_in[3];
    const float* gamma = (const float*)d_in[4];
    const float* beta  = (const float*)d_in[5];
    const int*   cnt   = (const int*)d_in[6];

    int T = in_sizes[0] / C_IN;
    int F = in_sizes[6];
    int numTiles = (T + TILE_M - 1) / TILE_M;

    int sms = 148;
    cudaDeviceGetAttribute(&sms, cudaDevAttrMultiProcessorCount, 0);
    cudaFuncSetAttribute(gemm_mma_kernel, cudaFuncAttributeMaxDynamicSharedMemorySize, SMEM_GEMM);

    int nb = (F + 1023) / 1024;
    scan1_kernel<<<nb, 1024>>>(cnt, F);
    scan2_kernel<<<1, 1024>>>(nb);
    scan3_kernel<<<nb, 1024>>>(F);

    gemm_mma_kernel<<<2 * sms, 256, SMEM_GEMM>>>(X, BARY, W, T, numTiles);

    zero_stats_kernel<<<1, 128>>>();
    facet_kernel<<<2048, 256>>>(cnt, bias, F);

    bn_kernel<<<2048, 256>>>(gamma, beta, (float*)d_out, F);
}

// round 7
// speedup vs baseline: 1.6277x; 1.0809x over previous
#include <cuda_runtime.h>
#include <cuda_fp16.h>
#include <math.h>
#include <stdint.h>

#define C_IN   64
#define C_OUT  64
#define NBASIS 9
#define TILE_M 128
#define MAX_T  1600000
#define MAX_F  400000
#define BN_EPS 1e-3f

// ---- scratch (device globals; no allocation allowed) ----
__device__ __half g_contrib[(size_t)MAX_T * C_OUT];  // 204.8 MB (fp16)
__device__ float  g_prebn[(size_t)MAX_F * C_OUT];    // 102.4 MB
__device__ int    g_offs[MAX_F];
__device__ int    g_blk[1024];
__device__ float  g_stats[2 * C_OUT];

// ================= exclusive-scan of num_texture =================
__global__ void scan1_kernel(const int* __restrict__ cnt, int F) {
    __shared__ int s[1024];
    int tid = threadIdx.x;
    int f = blockIdx.x * 1024 + tid;
    int c = (f < F) ? cnt[f] : 0;
    s[tid] = c;
    __syncthreads();
    for (int off = 1; off < 1024; off <<= 1) {
        int v = (tid >= off) ? s[tid - off] : 0;
        __syncthreads();
        s[tid] += v;
        __syncthreads();
    }
    if (f < F) g_offs[f] = s[tid] - c;
    if (tid == 1023) g_blk[blockIdx.x] = s[1023];
}
__global__ void scan2_kernel(int nb) {
    __shared__ int s[1024];
    int tid = threadIdx.x;
    int c = (tid < nb) ? g_blk[tid] : 0;
    s[tid] = c;
    __syncthreads();
    for (int off = 1; off < 1024; off <<= 1) {
        int v = (tid >= off) ? s[tid - off] : 0;
        __syncthreads();
        s[tid] += v;
        __syncthreads();
    }
    if (tid < nb) g_blk[tid] = s[tid] - c;
}
__global__ void scan3_kernel(int F) {
    int f = blockIdx.x * 1024 + threadIdx.x;
    if (f < F) g_offs[f] += g_blk[blockIdx.x];
}

// ================= mma.sync GEMM: ldmatrix + 2 CTA/SM + reg prefetch ======
// contrib[t,o] = sum_k bary[t,k] * ( sum_i x[t,i] * W[o,i,k] )
//
// SMEM per CTA (96768 B -> two CTAs fit in 228KB):
//   Wh : [kb*64+o] rows of 128 B, XOR-swizzled 16B chunks   = 73728 B
//   Ax : [t] rows, pad-72 halfs (144 B)                     = 18432 B
//   Bs : [t*9 + kb] fp32                                    =  4608 B
#define SM_W      0
#define SM_AX     73728
#define SM_BS     92160
#define SMEM_GEMM 96768

#define MMA16816(d, a0, a1, a2, a3, b0, b1)                                 \
    asm volatile(                                                           \
        "mma.sync.aligned.m16n8k16.row.col.f32.f16.f16.f32 "                \
        "{%0,%1,%2,%3},{%4,%5,%6,%7},{%8,%9},{%0,%1,%2,%3};"                \
        : "+f"((d)[0]), "+f"((d)[1]), "+f"((d)[2]), "+f"((d)[3])            \
        : "r"(a0), "r"(a1), "r"(a2), "r"(a3), "r"(b0), "r"(b1))

__device__ __forceinline__ void ldsm4(uint32_t* r, uint32_t addr) {
    asm volatile("ldmatrix.sync.aligned.m8n8.x4.shared.b16 {%0,%1,%2,%3}, [%4];"
                 : "=r"(r[0]), "=r"(r[1]), "=r"(r[2]), "=r"(r[3]) : "r"(addr));
}

__global__ void __launch_bounds__(256, 2) gemm_mma_kernel(
    const float* __restrict__ X,     // [T, 64]
    const float* __restrict__ BARY,  // [T, 9]
    const float* __restrict__ W,     // [64, 64, 9]  (o, i, k)
    int T, int numTiles)
{
    extern __shared__ char sm[];
    const uint32_t smb = (uint32_t)__cvta_generic_to_shared(sm);
    float* Bs = (float*)(sm + SM_BS);

    const int tid  = threadIdx.x;
    const int wid  = tid >> 5;
    const int lane = tid & 31;
    const int gid  = lane >> 2;
    const int warp_m = wid >> 1;     // 0..3
    const int warp_n = wid & 1;      // 0..1
    const int rbase  = warp_m * 32;

    // ---- convert W once: swizzled rows [kb*64+o][i], 128B rows ----
    for (int idx = tid; idx < C_OUT * C_IN * NBASIS; idx += 256) {
        int o   = idx / (C_IN * NBASIS);
        int rem = idx - o * (C_IN * NBASIS);
        int i   = rem / NBASIS;
        int k   = rem - i * NBASIS;
        uint32_t byte = (uint32_t)(k * 64 + o) * 128
                      + ((((uint32_t)i >> 3) ^ (uint32_t)(o & 7)) << 4)
                      + (i & 7) * 2;
        *(__half*)(sm + byte) = __float2half_rn(W[idx]);
    }

    // ---- per-thread LDSM addresses ----
    // A (pad-72 rows, 144B): lanes 0-15 -> rows (l&15), lanes>=16 -> col-block 1
    uint32_t a_base[2];
    #pragma unroll
    for (int mt = 0; mt < 2; mt++)
        a_base[mt] = smb + SM_AX
                   + (uint32_t)(rbase + mt * 16 + (lane & 15)) * 144
                   + ((lane >> 4) << 4);
    // B (swizzled 128B rows): pair p covers nt=2p,2p+1
    uint32_t b_base[2];
    int s_p[2];
    const int kh = (lane >> 3) & 1;
    #pragma unroll
    for (int p = 0; p < 2; p++) {
        int n_local = warp_n * 32 + p * 16 + ((lane >> 4) & 1) * 8 + (lane & 7);
        b_base[p] = smb + SM_W + (uint32_t)n_local * 128;
        s_p[p] = n_local & 7;
    }

    // ---- prefetch lane mapping ----
    const int prow = tid >> 1;       // 0..127
    const int phf  = tid & 1;
    const int kb0  = phf ? 5 : 0;
    const int nby  = phf ? 4 : 5;

    uint32_t pk[16];
    float    by[5];

    int tile = blockIdx.x;
    {   // prologue prefetch
        int t = tile * TILE_M + prow;
        if (t < T) {
            const float4* xp = (const float4*)(X + (size_t)t * C_IN + phf * 32);
            #pragma unroll
            for (int j = 0; j < 8; j++) {
                float4 v = xp[j];
                __half2 h0 = __floats2half2_rn(v.x, v.y);
                __half2 h1 = __floats2half2_rn(v.z, v.w);
                pk[2 * j]     = *(uint32_t*)&h0;
                pk[2 * j + 1] = *(uint32_t*)&h1;
            }
            #pragma unroll
            for (int j = 0; j < 5; j++)
                if (j < nby) by[j] = BARY[(size_t)t * NBASIS + kb0 + j];
        } else {
            #pragma unroll
            for (int j = 0; j < 16; j++) pk[j] = 0u;
            #pragma unroll
            for (int j = 0; j < 5; j++) by[j] = 0.0f;
        }
    }
    __syncthreads();   // W ready

    for (; tile < numTiles; tile += gridDim.x) {
        const int t0 = tile * TILE_M;

        // ---- store phase: regs -> SMEM ----
        {
            uint4* dst = (uint4*)(sm + SM_AX + prow * 144 + phf * 64);
            #pragma unroll
            for (int c = 0; c < 4; c++)
                dst[c] = make_uint4(pk[4 * c], pk[4 * c + 1], pk[4 * c + 2], pk[4 * c + 3]);
            #pragma unroll
            for (int j = 0; j < 5; j++)
                if (j < nby) Bs[prow * NBASIS + kb0 + j] = by[j];
        }
        __syncthreads();

        // ---- prefetch next tile (hidden under MMA below) ----
        {
            int ntile = tile + gridDim.x;
            if (ntile < numTiles) {
                int t = ntile * TILE_M + prow;
                if (t < T) {
                    const float4* xp = (const float4*)(X + (size_t)t * C_IN + phf * 32);
                    #pragma unroll
                    for (int j = 0; j < 8; j++) {
                        float4 v = xp[j];
                        __half2 h0 = __floats2half2_rn(v.x, v.y);
                        __half2 h1 = __floats2half2_rn(v.z, v.w);
                        pk[2 * j]     = *(uint32_t*)&h0;
                        pk[2 * j + 1] = *(uint32_t*)&h1;
                    }
                    #pragma unroll
                    for (int j = 0; j < 5; j++)
                        if (j < nby) by[j] = BARY[(size_t)t * NBASIS + kb0 + j];
                } else {
                    #pragma unroll
                    for (int j = 0; j < 16; j++) pk[j] = 0u;
                    #pragma unroll
                    for (int j = 0; j < 5; j++) by[j] = 0.0f;
                }
            }
        }

        float acc[2][4][4];
        #pragma unroll
        for (int mt = 0; mt < 2; mt++)
            #pragma unroll
            for (int nt = 0; nt < 4; nt++)
                #pragma unroll
                for (int e = 0; e < 4; e++) acc[mt][nt][e] = 0.0f;

        #pragma unroll 1
        for (int kb = 0; kb < NBASIS; kb++) {
            float tac[2][4][4];
            #pragma unroll
            for (int mt = 0; mt < 2; mt++)
                #pragma unroll
                for (int nt = 0; nt < 4; nt++)
                    #pragma unroll
                    for (int e = 0; e < 4; e++) tac[mt][nt][e] = 0.0f;

            const uint32_t kb_off = (uint32_t)kb * 8192;

            #pragma unroll
            for (int ks = 0; ks < 4; ks++) {
                uint32_t a0[4], a1[4];
                ldsm4(a0, a_base[0] + ks * 32);
                ldsm4(a1, a_base[1] + ks * 32);
                #pragma unroll
                for (int p = 0; p < 2; p++) {
                    uint32_t b[4];
                    uint32_t chunk = (uint32_t)(((ks << 1) | kh) ^ s_p[p]) << 4;
                    ldsm4(b, b_base[p] + kb_off + chunk);
                    MMA16816(tac[0][2 * p],     a0[0], a0[1], a0[2], a0[3], b[0], b[1]);
                    MMA16816(tac[1][2 * p],     a1[0], a1[1], a1[2], a1[3], b[0], b[1]);
                    MMA16816(tac[0][2 * p + 1], a0[0], a0[1], a0[2], a0[3], b[2], b[3]);
                    MMA16816(tac[1][2 * p + 1], a1[0], a1[1], a1[2], a1[3], b[2], b[3]);
                }
            }

            // fold with fp32 bary (off the MMA critical path)
            #pragma unroll
            for (int mt = 0; mt < 2; mt++) {
                float blo = Bs[(rbase + mt * 16 + gid) * NBASIS + kb];
                float bhi = Bs[(rbase + mt * 16 + gid + 8) * NBASIS + kb];
                #pragma unroll
                for (int nt = 0; nt < 4; nt++) {
                    acc[mt][nt][0] += blo * tac[mt][nt][0];
                    acc[mt][nt][1] += blo * tac[mt][nt][1];
                    acc[mt][nt][2] += bhi * tac[mt][nt][2];
                    acc[mt][nt][3] += bhi * tac[mt][nt][3];
                }
            }
        }

        // ---- store 32x32 warp tile as fp16 ----
        const int tid4 = lane & 3;
        #pragma unroll
        for (int mt = 0; mt < 2; mt++) {
            int t = t0 + rbase + mt * 16 + gid;
            #pragma unroll
            for (int nt = 0; nt < 4; nt++) {
                int col = warp_n * 32 + nt * 8 + tid4 * 2;
                if (t < T) {
                    __half2 h = __floats2half2_rn(acc[mt][nt][0], acc[mt][nt][1]);
                    *(__half2*)&g_contrib[(size_t)t * C_OUT + col] = h;
                }
                if (t + 8 < T) {
                    __half2 h = __floats2half2_rn(acc[mt][nt][2], acc[mt][nt][3]);
                    *(__half2*)&g_contrib[(size_t)(t + 8) * C_OUT + col] = h;
                }
            }
        }
        __syncthreads();   // all reads of Ax/Bs done before next store phase
    }
}

// ================= facet mean + bias + relu + fused BN stats =================
__global__ void facet_kernel(const int* __restrict__ cnt,
                             const float* __restrict__ bias, int F) {
    __shared__ float ssum[64], ssq[64];
    int tid = threadIdx.x;
    if (tid < 64) { ssum[tid] = 0.0f; ssq[tid] = 0.0f; }
    __syncthreads();

    int gw   = (blockIdx.x * blockDim.x + tid) >> 5;
    int lane = tid & 31;
    int nw   = (gridDim.x * blockDim.x) >> 5;
    float b0 = bias[2 * lane];
    float b1 = bias[2 * lane + 1];
    float a0 = 0.0f, a1 = 0.0f, q0 = 0.0f, q1 = 0.0f;

    for (int f = gw; f < F; f += nw) {
        int start = g_offs[f];
        int c = cnt[f];
        float s0 = 0.0f, s1 = 0.0f;
        for (int r = 0; r < c; r++) {
            const __half2* row = (const __half2*)(g_contrib + (size_t)(start + r) * C_OUT);
            float2 v = __half22float2(row[lane]);
            s0 += v.x;
            s1 += v.y;
        }
        float inv = (c > 0) ? (1.0f / (float)c) : 0.0f;
        float v0 = fmaxf(s0 * inv + b0, 0.0f);
        float v1 = fmaxf(s1 * inv + b1, 0.0f);
        *(float2*)&g_prebn[(size_t)f * C_OUT + 2 * lane] = make_float2(v0, v1);
        a0 += v0; q0 += v0 * v0;
        a1 += v1; q1 += v1 * v1;
    }
    atomicAdd(&ssum[2 * lane],     a0);
    atomicAdd(&ssq[2 * lane],      q0);
    atomicAdd(&ssum[2 * lane + 1], a1);
    atomicAdd(&ssq[2 * lane + 1],  q1);
    __syncthreads();
    if (tid < 64) {
        atomicAdd(&g_stats[tid],      ssum[tid]);
        atomicAdd(&g_stats[64 + tid], ssq[tid]);
    }
}

__global__ void zero_stats_kernel() {
    if (threadIdx.x < 2 * C_OUT) g_stats[threadIdx.x] = 0.0f;
}

// ================= batchnorm apply =================
__global__ void bn_kernel(const float* __restrict__ gamma,
                          const float* __restrict__ beta,
                          float* __restrict__ out, int F) {
    int idx = blockIdx.x * blockDim.x + threadIdx.x;
    int total = F * (C_OUT / 4);
    float invF = 1.0f / (float)F;
    for (; idx < total; idx += gridDim.x * blockDim.x) {
        int o = (idx & 15) * 4;
        float4 v = *(const float4*)&g_prebn[(size_t)idx * 4];
        float4 r;
        #pragma unroll
        for (int j = 0; j < 4; j++) {
            float mu  = g_stats[o + j] * invF;
            float var = g_stats[C_OUT + o + j] * invF - mu * mu;
            float sc  = rsqrtf(var + BN_EPS) * gamma[o + j];
            float bb  = beta[o + j];
            float x   = (&v.x)[j];
            (&r.x)[j] = (x - mu) * sc + bb;
        }
        *(float4*)&out[(size_t)idx * 4] = r;
    }
}

// ================= launch =================
extern "C" void kernel_launch(void* const* d_in, const int* in_sizes, int n_in,
                              void* d_out, int out_size) {
    const float* X     = (const float*)d_in[0];
    const float* BARY  = (const float*)d_in[1];
    const float* W     = (const float*)d_in[2];
    const float* bias  = (const float*)d_in[3];
    const float* gamma = (const float*)d_in[4];
    const float* beta  = (const float*)d_in[5];
    const int*   cnt   = (const int*)d_in[6];

    int T = in_sizes[0] / C_IN;
    int F = in_sizes[6];
    int numTiles = (T + TILE_M - 1) / TILE_M;

    int sms = 148;
    cudaDeviceGetAttribute(&sms, cudaDevAttrMultiProcessorCount, 0);
    cudaFuncSetAttribute(gemm_mma_kernel, cudaFuncAttributeMaxDynamicSharedMemorySize, SMEM_GEMM);

    int nb = (F + 1023) / 1024;
    scan1_kernel<<<nb, 1024>>>(cnt, F);
    scan2_kernel<<<1, 1024>>>(nb);
    scan3_kernel<<<nb, 1024>>>(F);

    gemm_mma_kernel<<<2 * sms, 256, SMEM_GEMM>>>(X, BARY, W, T, numTiles);

    zero_stats_kernel<<<1, 128>>>();
    facet_kernel<<<2048, 256>>>(cnt, bias, F);

    bn_kernel<<<2048, 256>>>(gamma, beta, (float*)d_out, F);
}

// round 8
// speedup vs baseline: 1.7930x; 1.1015x over previous
#include <cuda_runtime.h>
#include <cuda_fp16.h>
#include <math.h>
#include <stdint.h>

#define C_IN   64
#define C_OUT  64
#define NBASIS 9
#define TILE_M 128
#define MAX_T  1600000
#define MAX_F  400000
#define BN_EPS 1e-3f

// ---- scratch (device globals; no allocation allowed) ----
__device__ __half g_contrib[(size_t)MAX_T * C_OUT];  // 204.8 MB (fp16)
__device__ float  g_prebn[(size_t)MAX_F * C_OUT];    // 102.4 MB
__device__ int    g_offs[MAX_F];
__device__ int    g_blk[1024];
__device__ float  g_stats[2 * C_OUT];

// ================= exclusive-scan of num_texture =================
__global__ void scan1_kernel(const int* __restrict__ cnt, int F) {
    __shared__ int s[1024];
    int tid = threadIdx.x;
    int f = blockIdx.x * 1024 + tid;
    int c = (f < F) ? cnt[f] : 0;
    s[tid] = c;
    __syncthreads();
    for (int off = 1; off < 1024; off <<= 1) {
        int v = (tid >= off) ? s[tid - off] : 0;
        __syncthreads();
        s[tid] += v;
        __syncthreads();
    }
    if (f < F) g_offs[f] = s[tid] - c;
    if (tid == 1023) g_blk[blockIdx.x] = s[1023];
}
__global__ void scan2_kernel(int nb) {
    __shared__ int s[1024];
    int tid = threadIdx.x;
    int c = (tid < nb) ? g_blk[tid] : 0;
    s[tid] = c;
    __syncthreads();
    for (int off = 1; off < 1024; off <<= 1) {
        int v = (tid >= off) ? s[tid - off] : 0;
        __syncthreads();
        s[tid] += v;
        __syncthreads();
    }
    if (tid < nb) g_blk[tid] = s[tid] - c;
}
__global__ void scan3_kernel(int F) {
    int f = blockIdx.x * 1024 + threadIdx.x;
    if (f < F) g_offs[f] += g_blk[blockIdx.x];
}

// ================= mma.sync GEMM: hoisted A frags + HMUL2 bary fold =======
// contrib[t,o] = sum_k ( (x[t,:] * bary[t,k]) fp16 ) @ W_k[o,:]^T
//
// SMEM per CTA (96912 B -> two CTAs per SM):
//   Wh  : [kb*64+o] rows of 128 B, XOR-swizzled 16B chunks  = 73728 B
//   Ax  : [t] rows, pad-72 halfs (144 B)                    = 18432 B
//   Bsh : 2 x [kb*132 + t] fp16                             =  4752 B
#define SM_W      0
#define SM_AX     73728
#define SM_BS     92160
#define BS_HALFS  1188            // 9 * 132
#define SMEM_GEMM 96912

#define MMA16816(d, a0, a1, a2, a3, b0, b1)                                 \
    asm volatile(                                                           \
        "mma.sync.aligned.m16n8k16.row.col.f32.f16.f16.f32 "                \
        "{%0,%1,%2,%3},{%4,%5,%6,%7},{%8,%9},{%0,%1,%2,%3};"                \
        : "+f"((d)[0]), "+f"((d)[1]), "+f"((d)[2]), "+f"((d)[3])            \
        : "r"(a0), "r"(a1), "r"(a2), "r"(a3), "r"(b0), "r"(b1))

__device__ __forceinline__ void ldsm4(uint32_t* r, uint32_t addr) {
    asm volatile("ldmatrix.sync.aligned.m8n8.x4.shared.b16 {%0,%1,%2,%3}, [%4];"
                 : "=r"(r[0]), "=r"(r[1]), "=r"(r[2]), "=r"(r[3]) : "r"(addr));
}
__device__ __forceinline__ uint32_t hmul2u(uint32_t a, uint32_t b) {
    __half2 r = __hmul2(*(__half2*)&a, *(__half2*)&b);
    return *(uint32_t*)&r;
}

__global__ void __launch_bounds__(256, 2) gemm_mma_kernel(
    const float* __restrict__ X,     // [T, 64]
    const float* __restrict__ BARY,  // [T, 9]
    const float* __restrict__ W,     // [64, 64, 9]  (o, i, k)
    int T, int numTiles)
{
    extern __shared__ char sm[];
    const uint32_t smb = (uint32_t)__cvta_generic_to_shared(sm);
    __half* Bsh = (__half*)(sm + SM_BS);

    const int tid  = threadIdx.x;
    const int wid  = tid >> 5;
    const int lane = tid & 31;
    const int gid  = lane >> 2;
    const int warp_m = wid >> 1;     // 0..3
    const int warp_n = wid & 1;      // 0..1
    const int rbase  = warp_m * 32;

    // ---- convert W once: swizzled rows [kb*64+o][i], 128B rows ----
    for (int idx = tid; idx < C_OUT * C_IN * NBASIS; idx += 256) {
        int o   = idx / (C_IN * NBASIS);
        int rem = idx - o * (C_IN * NBASIS);
        int i   = rem / NBASIS;
        int k   = rem - i * NBASIS;
        uint32_t byte = (uint32_t)(k * 64 + o) * 128
                      + ((((uint32_t)i >> 3) ^ (uint32_t)(o & 7)) << 4)
                      + (i & 7) * 2;
        *(__half*)(sm + byte) = __float2half_rn(W[idx]);
    }

    // ---- per-thread LDSM addresses ----
    uint32_t a_base[2];
    #pragma unroll
    for (int mt = 0; mt < 2; mt++)
        a_base[mt] = smb + SM_AX
                   + (uint32_t)(rbase + mt * 16 + (lane & 15)) * 144
                   + ((lane >> 4) << 4);
    uint32_t b_base[2];
    int s_p[2];
    const int kh = (lane >> 3) & 1;
    #pragma unroll
    for (int p = 0; p < 2; p++) {
        int n_local = warp_n * 32 + p * 16 + ((lane >> 4) & 1) * 8 + (lane & 7);
        b_base[p] = smb + SM_W + (uint32_t)n_local * 128;
        s_p[p] = n_local & 7;
    }

    // ---- prefetch lane mapping ----
    const int prow = tid >> 1;       // 0..127
    const int phf  = tid & 1;
    const int kb0  = phf ? 5 : 0;
    const int nby  = phf ? 4 : 5;

    uint32_t pk[16];
    float    by[5];

    int tile = blockIdx.x;
    {   // prologue prefetch
        int t = tile * TILE_M + prow;
        if (t < T) {
            const float4* xp = (const float4*)(X + (size_t)t * C_IN + phf * 32);
            #pragma unroll
            for (int j = 0; j < 8; j++) {
                float4 v = xp[j];
                __half2 h0 = __floats2half2_rn(v.x, v.y);
                __half2 h1 = __floats2half2_rn(v.z, v.w);
                pk[2 * j]     = *(uint32_t*)&h0;
                pk[2 * j + 1] = *(uint32_t*)&h1;
            }
            #pragma unroll
            for (int j = 0; j < 5; j++)
                if (j < nby) by[j] = BARY[(size_t)t * NBASIS + kb0 + j];
        } else {
            #pragma unroll
            for (int j = 0; j < 16; j++) pk[j] = 0u;
            #pragma unroll
            for (int j = 0; j < 5; j++) by[j] = 0.0f;
        }
    }
    __syncthreads();   // W ready

    int buf = 0;
    for (; tile < numTiles; tile += gridDim.x) {
        const int t0 = tile * TILE_M;

        // ---- store phase: regs -> SMEM ----
        {
            uint4* dst = (uint4*)(sm + SM_AX + prow * 144 + phf * 64);
            #pragma unroll
            for (int c = 0; c < 4; c++)
                dst[c] = make_uint4(pk[4 * c], pk[4 * c + 1], pk[4 * c + 2], pk[4 * c + 3]);
            __half* BsB = Bsh + buf * BS_HALFS;
            #pragma unroll
            for (int j = 0; j < 5; j++)
                if (j < nby) BsB[(kb0 + j) * 132 + prow] = __float2half_rn(by[j]);
        }
        __syncthreads();   // barrier A: stores visible

        // ---- load A fragments ONCE per tile (regs for whole MMA phase) ----
        uint32_t afr[2][4][4];
        #pragma unroll
        for (int mt = 0; mt < 2; mt++)
            #pragma unroll
            for (int ks = 0; ks < 4; ks++)
                ldsm4(afr[mt][ks], a_base[mt] + ks * 32);
        __syncthreads();   // barrier B: Ax readable no more -> free for next tile

        // ---- prefetch next tile (hidden under MMA below) ----
        {
            int ntile = tile + gridDim.x;
            if (ntile < numTiles) {
                int t = ntile * TILE_M + prow;
                if (t < T) {
                    const float4* xp = (const float4*)(X + (size_t)t * C_IN + phf * 32);
                    #pragma unroll
                    for (int j = 0; j < 8; j++) {
                        float4 v = xp[j];
                        __half2 h0 = __floats2half2_rn(v.x, v.y);
                        __half2 h1 = __floats2half2_rn(v.z, v.w);
                        pk[2 * j]     = *(uint32_t*)&h0;
                        pk[2 * j + 1] = *(uint32_t*)&h1;
                    }
                    #pragma unroll
                    for (int j = 0; j < 5; j++)
                        if (j < nby) by[j] = BARY[(size_t)t * NBASIS + kb0 + j];
                } else {
                    #pragma unroll
                    for (int j = 0; j < 16; j++) pk[j] = 0u;
                    #pragma unroll
                    for (int j = 0; j < 5; j++) by[j] = 0.0f;
                }
            }
        }

        const __half* BsB = Bsh + buf * BS_HALFS;

        float acc[2][4][4];
        #pragma unroll
        for (int mt = 0; mt < 2; mt++)
            #pragma unroll
            for (int nt = 0; nt < 4; nt++)
                #pragma unroll
                for (int e = 0; e < 4; e++) acc[mt][nt][e] = 0.0f;

        #pragma unroll 1
        for (int kb = 0; kb < NBASIS; kb++) {
            // bary half2 broadcasts (rows gid / gid+8 per mt)
            uint32_t bb0[2], bb1[2];
            #pragma unroll
            for (int mt = 0; mt < 2; mt++) {
                int r = rbase + mt * 16 + gid;
                __half2 h0 = __half2half2(BsB[kb * 132 + r]);
                __half2 h1 = __half2half2(BsB[kb * 132 + r + 8]);
                bb0[mt] = *(uint32_t*)&h0;
                bb1[mt] = *(uint32_t*)&h1;
            }

            const uint32_t kb_off = (uint32_t)kb * 8192;

            #pragma unroll
            for (int ks = 0; ks < 4; ks++) {
                // bary-scaled A fragments (fp16 HMUL2, off LDSM pipe)
                uint32_t sa0[4], sa1[4];
                sa0[0] = hmul2u(afr[0][ks][0], bb0[0]);
                sa0[1] = hmul2u(afr[0][ks][1], bb1[0]);
                sa0[2] = hmul2u(afr[0][ks][2], bb0[0]);
                sa0[3] = hmul2u(afr[0][ks][3], bb1[0]);
                sa1[0] = hmul2u(afr[1][ks][0], bb0[1]);
                sa1[1] = hmul2u(afr[1][ks][1], bb1[1]);
                sa1[2] = hmul2u(afr[1][ks][2], bb0[1]);
                sa1[3] = hmul2u(afr[1][ks][3], bb1[1]);
                #pragma unroll
                for (int p = 0; p < 2; p++) {
                    uint32_t b[4];
                    uint32_t chunk = (uint32_t)(((ks << 1) | kh) ^ s_p[p]) << 4;
                    ldsm4(b, b_base[p] + kb_off + chunk);
                    MMA16816(acc[0][2 * p],     sa0[0], sa0[1], sa0[2], sa0[3], b[0], b[1]);
                    MMA16816(acc[1][2 * p],     sa1[0], sa1[1], sa1[2], sa1[3], b[0], b[1]);
                    MMA16816(acc[0][2 * p + 1], sa0[0], sa0[1], sa0[2], sa0[3], b[2], b[3]);
                    MMA16816(acc[1][2 * p + 1], sa1[0], sa1[1], sa1[2], sa1[3], b[2], b[3]);
                }
            }
        }

        // ---- store 32x32 warp tile as fp16 ----
        const int tid4 = lane & 3;
        #pragma unroll
        for (int mt = 0; mt < 2; mt++) {
            int t = t0 + rbase + mt * 16 + gid;
            #pragma unroll
            for (int nt = 0; nt < 4; nt++) {
                int col = warp_n * 32 + nt * 8 + tid4 * 2;
                if (t < T) {
                    __half2 h = __floats2half2_rn(acc[mt][nt][0], acc[mt][nt][1]);
                    *(__half2*)&g_contrib[(size_t)t * C_OUT + col] = h;
                }
                if (t + 8 < T) {
                    __half2 h = __floats2half2_rn(acc[mt][nt][2], acc[mt][nt][3]);
                    *(__half2*)&g_contrib[(size_t)(t + 8) * C_OUT + col] = h;
                }
            }
        }
        buf ^= 1;
        // No end barrier needed: Ax reuse guarded by barriers A/B; bary is
        // double-buffered; W is read-only after init.
    }
}

// ================= facet mean + bias + relu + fused BN stats =================
__global__ void facet_kernel(const int* __restrict__ cnt,
                             const float* __restrict__ bias, int F) {
    __shared__ float ssum[64], ssq[64];
    int tid = threadIdx.x;
    if (tid < 64) { ssum[tid] = 0.0f; ssq[tid] = 0.0f; }
    __syncthreads();

    int gw   = (blockIdx.x * blockDim.x + tid) >> 5;
    int lane = tid & 31;
    int nw   = (gridDim.x * blockDim.x) >> 5;
    float b0 = bias[2 * lane];
    float b1 = bias[2 * lane + 1];
    float a0 = 0.0f, a1 = 0.0f, q0 = 0.0f, q1 = 0.0f;

    for (int f = gw; f < F; f += nw) {
        int start = g_offs[f];
        int c = cnt[f];
        float s0 = 0.0f, s1 = 0.0f;
        for (int r = 0; r < c; r++) {
            const __half2* row = (const __half2*)(g_contrib + (size_t)(start + r) * C_OUT);
            float2 v = __half22float2(row[lane]);
            s0 += v.x;
            s1 += v.y;
        }
        float inv = (c > 0) ? (1.0f / (float)c) : 0.0f;
        float v0 = fmaxf(s0 * inv + b0, 0.0f);
        float v1 = fmaxf(s1 * inv + b1, 0.0f);
        *(float2*)&g_prebn[(size_t)f * C_OUT + 2 * lane] = make_float2(v0, v1);
        a0 += v0; q0 += v0 * v0;
        a1 += v1; q1 += v1 * v1;
    }
    atomicAdd(&ssum[2 * lane],     a0);
    atomicAdd(&ssq[2 * lane],      q0);
    atomicAdd(&ssum[2 * lane + 1], a1);
    atomicAdd(&ssq[2 * lane + 1],  q1);
    __syncthreads();
    if (tid < 64) {
        atomicAdd(&g_stats[tid],      ssum[tid]);
        atomicAdd(&g_stats[64 + tid], ssq[tid]);
    }
}

__global__ void zero_stats_kernel() {
    if (threadIdx.x < 2 * C_OUT) g_stats[threadIdx.x] = 0.0f;
}

// ================= batchnorm apply =================
__global__ void bn_kernel(const float* __restrict__ gamma,
                          const float* __restrict__ beta,
                          float* __restrict__ out, int F) {
    int idx = blockIdx.x * blockDim.x + threadIdx.x;
    int total = F * (C_OUT / 4);
    float invF = 1.0f / (float)F;
    for (; idx < total; idx += gridDim.x * blockDim.x) {
        int o = (idx & 15) * 4;
        float4 v = *(const float4*)&g_prebn[(size_t)idx * 4];
        float4 r;
        #pragma unroll
        for (int j = 0; j < 4; j++) {
            float mu  = g_stats[o + j] * invF;
            float var = g_stats[C_OUT + o + j] * invF - mu * mu;
            float sc  = rsqrtf(var + BN_EPS) * gamma[o + j];
            float bb  = beta[o + j];
            float x   = (&v.x)[j];
            (&r.x)[j] = (x - mu) * sc + bb;
        }
        *(float4*)&out[(size_t)idx * 4] = r;
    }
}

// ================= launch =================
extern "C" void kernel_launch(void* const* d_in, const int* in_sizes, int n_in,
                              void* d_out, int out_size) {
    const float* X     = (const float*)d_in[0];
    const float* BARY  = (const float*)d_in[1];
    const float* W     = (const float*)d_in[2];
    const float* bias  = (const float*)d_in[3];
    const float* gamma = (const float*)d_in[4];
    const float* beta  = (const float*)d_in[5];
    const int*   cnt   = (const int*)d_in[6];

    int T = in_sizes[0] / C_IN;
    int F = in_sizes[6];
    int numTiles = (T + TILE_M - 1) / TILE_M;

    int sms = 148;
    cudaDeviceGetAttribute(&sms, cudaDevAttrMultiProcessorCount, 0);
    cudaFuncSetAttribute(gemm_mma_kernel, cudaFuncAttributeMaxDynamicSharedMemorySize, SMEM_GEMM);

    int nb = (F + 1023) / 1024;
    scan1_kernel<<<nb, 1024>>>(cnt, F);
    scan2_kernel<<<1, 1024>>>(nb);
    scan3_kernel<<<nb, 1024>>>(F);

    gemm_mma_kernel<<<2 * sms, 256, SMEM_GEMM>>>(X, BARY, W, T, numTiles);

    zero_stats_kernel<<<1, 128>>>();
    facet_kernel<<<2048, 256>>>(cnt, bias, F);

    bn_kernel<<<2048, 256>>>(gamma, beta, (float*)d_out, F);
}